// round 6
// baseline (speedup 1.0000x reference)
#include <cuda_runtime.h>
#include <cuda_fp16.h>
#include <math.h>

// Problem constants
#define B_TOTAL 512
#define T_STEPS 1024
#define F_IN    32
#define HID     128
#define BC      4                  // batch rows per block
#define NBLK    (B_TOTAL / BC)     // 128 blocks
#define NTHR    256                // 8 warps: 2 per SMSP. thread = (half, j)
#define W1S_K2  16                 // layer1 k2-pairs staged in smem (8 per half)

// fp16 weights, k-pair-major: half idx = k2*1024 + j*8 + (k&1)*4 + gate
// -> uint4 element (k2, j) holds k=2*k2 (8B: if-pair, go-pair) and k=2*k2+1 (8B)
__device__ __half g_W0p[160 * 512];   // layer0: k in [0,32)=Wih0, [32,160)=Whh0
__device__ __half g_W1p[256 * 512];   // layer1: k in [0,128)=Wih1, [128,256)=Whh1
__device__ float  g_B0[512];          // bih0+bhh0, gate-interleaved idx = 4*j+g
__device__ float  g_B1[512];

__global__ void pack_kernel(const float* __restrict__ Wih0, const float* __restrict__ Whh0,
                            const float* __restrict__ bih0, const float* __restrict__ bhh0,
                            const float* __restrict__ Wih1, const float* __restrict__ Whh1,
                            const float* __restrict__ bih1, const float* __restrict__ bhh1)
{
    int idx = blockIdx.x * blockDim.x + threadIdx.x;
    if (idx < 160 * 512) {
        int k2 = idx >> 10, rem = idx & 1023;
        int j = rem >> 3, p = (rem >> 2) & 1, g = rem & 3;
        int k = k2 * 2 + p, row = g * HID + j;
        float w = (k < F_IN) ? Wih0[row * F_IN + k] : Whh0[row * HID + (k - F_IN)];
        g_W0p[idx] = __float2half_rn(w);
    }
    if (idx < 256 * 512) {
        int k2 = idx >> 10, rem = idx & 1023;
        int j = rem >> 3, p = (rem >> 2) & 1, g = rem & 3;
        int k = k2 * 2 + p, row = g * HID + j;
        float w = (k < HID) ? Wih1[row * HID + k] : Whh1[row * HID + (k - HID)];
        g_W1p[idx] = __float2half_rn(w);
    }
    if (idx < 512) {
        int j = idx >> 2, g = idx & 3, row = g * HID + j;
        g_B0[idx] = bih0[row] + bhh0[row];
        g_B1[idx] = bih1[row] + bhh1[row];
    }
}

// ---- packed f32x2 helpers ----
__device__ __forceinline__ void upk2(unsigned long long v, float& lo, float& hi) {
    unsigned int a, b;
    asm("mov.b64 {%0, %1}, %2;" : "=r"(a), "=r"(b) : "l"(v));
    lo = __uint_as_float(a); hi = __uint_as_float(b);
}
__device__ __forceinline__ unsigned long long pkf2(float2 v) {
    unsigned long long r;
    asm("mov.b64 %0, {%1, %2};" : "=l"(r) : "r"(__float_as_uint(v.x)), "r"(__float_as_uint(v.y)));
    return r;
}
__device__ __forceinline__ void fma2(unsigned long long& d, unsigned long long a, unsigned long long b) {
    asm("fma.rn.f32x2 %0, %1, %2, %0;" : "+l"(d) : "l"(a), "l"(b));
}
__device__ __forceinline__ void add2(unsigned long long& d, unsigned long long a) {
    asm("add.rn.f32x2 %0, %0, %1;" : "+l"(d) : "l"(a));
}

__device__ __forceinline__ float sigf(float x) {
    return 1.0f / (1.0f + __expf(-x));
}
__device__ __forceinline__ float tanhfast(float x) {
    float cx = fminf(fmaxf(x, -15.f), 15.f);
    float e  = __expf(-2.f * cx);
    return (1.f - e) / (1.f + e);
}

// one uint4 = weights for 2 consecutive k of column j (if-pair, go-pair per k).
// acts: per row r, one LDS.128 over dup-array gives both k's broadcast operands.
template<typename AccT>
__device__ __forceinline__ void mac_k2(uint4 wv, const float2* actRow0, int rowStrideF2, int k2,
                                       AccT* accif, AccT* accgo)
{
    float2 wif0 = __half22float2(*reinterpret_cast<const __half2*>(&wv.x));
    float2 wgo0 = __half22float2(*reinterpret_cast<const __half2*>(&wv.y));
    float2 wif1 = __half22float2(*reinterpret_cast<const __half2*>(&wv.z));
    float2 wgo1 = __half22float2(*reinterpret_cast<const __half2*>(&wv.w));
    unsigned long long wif0p = pkf2(wif0), wgo0p = pkf2(wgo0);
    unsigned long long wif1p = pkf2(wif1), wgo1p = pkf2(wgo1);
    #pragma unroll
    for (int r = 0; r < BC; ++r) {
        const ulonglong2 av = *reinterpret_cast<const ulonglong2*>(actRow0 + (size_t)r * rowStrideF2 + 2 * k2);
        fma2(accif[r], wif0p, av.x);
        fma2(accgo[r], wgo0p, av.x);
        fma2(accif[r], wif1p, av.y);
        fma2(accgo[r], wgo1p, av.y);
    }
}

__global__ __launch_bounds__(NTHR, 1)
void lstm_main(const float* __restrict__ x,
               const float* __restrict__ ln_g, const float* __restrict__ ln_b,
               const float* __restrict__ hW1,  const float* __restrict__ hb1,
               const float* __restrict__ hW2,  const float* __restrict__ hb2,
               float* __restrict__ out)
{
    extern __shared__ char dsm[];              // [0,163840) = W0, [163840,196608) = W1 slice
    __shared__ float2 a0d[BC][160];            // dup acts: [0:32) x_t, [32:160) h0
    __shared__ float2 a1d[BC][256];            // dup acts: [0:128) h0_new, [128:256) h1
    __shared__ unsigned long long part[NTHR][4];
    __shared__ float red[BC][64];
    __shared__ float mv[BC][2];

    const int tid = threadIdx.x;
    const int j   = tid & 127;                 // hidden column
    const int h   = tid >> 7;                  // K-half
    const int bid = blockIdx.x;

    // ---- one-time: stage weights into smem ----
    {
        const uint4* s0 = reinterpret_cast<const uint4*>(g_W0p);
        uint4* d0 = reinterpret_cast<uint4*>(dsm);
        for (int i = tid; i < 160 * 512 * 2 / 16; i += NTHR) d0[i] = s0[i];
        // W1 slice: k2local 0..7 -> k2 0..7 (half0); 8..15 -> k2 64..71 (half1)
        const uint4* s1 = reinterpret_cast<const uint4*>(g_W1p);
        uint4* d1 = reinterpret_cast<uint4*>(dsm + 160 * 512 * 2);
        for (int i = tid; i < W1S_K2 * 128; i += NTHR) {
            int k2l = i >> 7, jj = i & 127;
            int k2 = (k2l < 8) ? k2l : (64 + k2l - 8);
            d1[i] = s1[k2 * 128 + jj];
        }
    }
    for (int i = tid; i < BC * 160; i += NTHR) (&a0d[0][0])[i] = make_float2(0.f, 0.f);
    for (int i = tid; i < BC * 256; i += NTHR) (&a1d[0][0])[i] = make_float2(0.f, 0.f);

    const uint4* __restrict__ W0s = reinterpret_cast<const uint4*>(dsm);
    const uint4* __restrict__ W1s = reinterpret_cast<const uint4*>(dsm + 160 * 512 * 2);
    const uint4* __restrict__ W1g = reinterpret_cast<const uint4*>(g_W1p);
    const float4 b0v = reinterpret_cast<const float4*>(g_B0)[j];
    const float4 b1v = reinterpret_cast<const float4*>(g_B1)[j];

    // cell state for the 2 rows this thread finalizes: rows 2h, 2h+1
    float c0[2] = {0.f, 0.f};
    float c1[2] = {0.f, 0.f};

    // L0 k2 range per half; L1 smem k2local + global k2 ranges per half
    const int l0_beg = h ? 40 : 0,  l0_end = l0_beg + 40;
    const int l1s_beg = h ? 8 : 0;                  // k2local
    const int l1g_beg = h ? 72 : 8, l1g_end = h ? 128 : 64;   // 56 each
    const int partner = (1 - h) * 128 + j;
    const int orow = 2 * (1 - h);

    const float* xbase = x + (size_t)(bid * BC) * T_STEPS * F_IN;
    const int xr = (tid & 127) >> 5, xk = tid & 31;          // tid<128 stages x
    const float* xsrc = xbase + (size_t)xr * T_STEPS * F_IN + xk;

    __syncthreads();   // weights + zeroed state visible

    for (int t = 0; t < T_STEPS; ++t) {
        // stage x_t duplicated (sync A also publishes last step's h1 writes)
        if (tid < 128) {
            float v = xsrc[t * F_IN];
            a0d[xr][xk] = make_float2(v, v);
        }
        __syncthreads();   // A

        // ---------------- layer 0 mac: half-K, all 4 rows, smem ----------------
        unsigned long long accif[BC] = {0, 0, 0, 0};
        unsigned long long accgo[BC] = {0, 0, 0, 0};
        #pragma unroll 4
        for (int k2 = l0_beg; k2 < l0_end; ++k2) {
            uint4 wv = W0s[k2 * 128 + j];
            mac_k2(wv, &a0d[0][0], 160, k2, accif, accgo);
        }
        // early prefetch of first 4 global W1 k2 (independent of activations)
        uint4 rbuf[4];
        #pragma unroll
        for (int q = 0; q < 4; ++q) rbuf[q] = W1g[(l1g_beg + q) * 128 + j];

        // exchange partials for the other half's rows
        part[tid][0] = accif[orow];     part[tid][1] = accgo[orow];
        part[tid][2] = accif[orow + 1]; part[tid][3] = accgo[orow + 1];
        __syncthreads();   // B: partials visible; all a0d reads done

        #pragma unroll
        for (int rr = 0; rr < 2; ++rr) {
            int r = 2 * h + rr;
            unsigned long long tif = accif[r], tgo = accgo[r];
            add2(tif, part[partner][2 * rr]);
            add2(tgo, part[partner][2 * rr + 1]);
            float gi, gf, gg, go;
            upk2(tif, gi, gf); upk2(tgo, gg, go);
            float ig = sigf(gi + b0v.x), fg = sigf(gf + b0v.y);
            float gv = tanhfast(gg + b0v.z), og = sigf(go + b0v.w);
            c0[rr] = fg * c0[rr] + ig * gv;
            float hh = og * tanhfast(c0[rr]);
            a0d[r][32 + j] = make_float2(hh, hh);
            a1d[r][j]      = make_float2(hh, hh);
        }
        __syncthreads();   // C: h0_new published

        // ---------------- layer 1 mac: half-K (smem slice + global stream) ----------------
        #pragma unroll
        for (int r = 0; r < BC; ++r) { accif[r] = 0; accgo[r] = 0; }
        #pragma unroll
        for (int k2l = l1s_beg; k2l < l1s_beg + 8; ++k2l) {
            uint4 wv = W1s[k2l * 128 + j];
            int k2 = (k2l < 8) ? k2l : (64 + k2l - 8);
            mac_k2(wv, &a1d[0][0], 256, k2, accif, accgo);
        }
        #pragma unroll 2
        for (int i = 0; i < 56; ++i) {
            uint4 wv = rbuf[i & 3];
            int nk = l1g_beg + i + 4;
            if (nk < l1g_end) rbuf[i & 3] = W1g[nk * 128 + j];
            int k2 = l1g_beg + i;
            mac_k2(wv, &a1d[0][0], 256, k2, accif, accgo);
        }

        part[tid][0] = accif[orow];     part[tid][1] = accgo[orow];
        part[tid][2] = accif[orow + 1]; part[tid][3] = accgo[orow + 1];
        __syncthreads();   // D: partials visible; all a1d reads done

        #pragma unroll
        for (int rr = 0; rr < 2; ++rr) {
            int r = 2 * h + rr;
            unsigned long long tif = accif[r], tgo = accgo[r];
            add2(tif, part[partner][2 * rr]);
            add2(tgo, part[partner][2 * rr + 1]);
            float gi, gf, gg, go;
            upk2(tif, gi, gf); upk2(tgo, gg, go);
            float ig = sigf(gi + b1v.x), fg = sigf(gf + b1v.y);
            float gv = tanhfast(gg + b1v.z), og = sigf(go + b1v.w);
            c1[rr] = fg * c1[rr] + ig * gv;
            float hh = og * tanhfast(c1[rr]);
            a1d[r][128 + j] = make_float2(hh, hh);
        }
        // next iteration's sync A publishes h1
    }
    __syncthreads();

    // ---------------- head: LayerNorm -> Linear(64) -> ReLU -> Linear(1) -> sigmoid ----
    if (tid < BC) {
        int r = tid;
        float s = 0.f;
        for (int k = 0; k < HID; ++k) s += a1d[r][128 + k].x;
        float mu = s * (1.f / HID);
        float v = 0.f;
        for (int k = 0; k < HID; ++k) { float d = a1d[r][128 + k].x - mu; v += d * d; }
        v *= (1.f / HID);
        mv[r][0] = mu;
        mv[r][1] = rsqrtf(v + 1e-5f);
    }
    __syncthreads();
    {
        int r = tid >> 6, u = tid & 63;        // 256 threads = 4 rows x 64 units
        float mu = mv[r][0], rs = mv[r][1];
        float acc = hb1[u];
        for (int k = 0; k < HID; ++k) {
            float lnv = (a1d[r][128 + k].x - mu) * rs * ln_g[k] + ln_b[k];
            acc += lnv * hW1[u * HID + k];
        }
        red[r][u] = fmaxf(acc, 0.f);
    }
    __syncthreads();
    if (tid < BC) {
        int r = tid;
        float y = hb2[0];
        for (int u = 0; u < 64; ++u) y += red[r][u] * hW2[u];
        out[bid * BC + r] = sigf(y);
    }
}

extern "C" void kernel_launch(void* const* d_in, const int* in_sizes, int n_in,
                              void* d_out, int out_size)
{
    const float* x    = (const float*)d_in[0];
    const float* Wih0 = (const float*)d_in[1];
    const float* Whh0 = (const float*)d_in[2];
    const float* bih0 = (const float*)d_in[3];
    const float* bhh0 = (const float*)d_in[4];
    const float* Wih1 = (const float*)d_in[5];
    const float* Whh1 = (const float*)d_in[6];
    const float* bih1 = (const float*)d_in[7];
    const float* bhh1 = (const float*)d_in[8];
    const float* ln_g = (const float*)d_in[9];
    const float* ln_b = (const float*)d_in[10];
    const float* W1   = (const float*)d_in[11];
    const float* b1   = (const float*)d_in[12];
    const float* W2   = (const float*)d_in[13];
    const float* b2   = (const float*)d_in[14];
    float* out = (float*)d_out;

    const int dyn_smem = 160 * 512 * 2 + W1S_K2 * 128 * 16;   // 163840 + 32768 = 196608
    cudaFuncSetAttribute(lstm_main, cudaFuncAttributeMaxDynamicSharedMemorySize, dyn_smem);

    pack_kernel<<<512, 256>>>(Wih0, Whh0, bih0, bhh0, Wih1, Whh1, bih1, bhh1);
    lstm_main<<<NBLK, NTHR, dyn_smem>>>(x, ln_g, ln_b, W1, b1, W2, b2, out);
}

// round 9
// speedup vs baseline: 1.6172x; 1.6172x over previous
#include <cuda_runtime.h>
#include <cuda_fp16.h>
#include <math.h>

// Problem constants
#define B_TOTAL 512
#define T_STEPS 1024
#define F_IN    32
#define HID     128
#define BC      4                  // batch rows per block
#define NBLK    (B_TOTAL / BC)     // 128 blocks
#define NTHR    256                // 8 warps, 2/SMSP. thread=(rh,j): rows {2rh,2rh+1}, col j
#define W1S     20                 // W1 k2-pairs resident in smem; k2 in [W1S,128) streamed

// fp16 weights, k-pair-major: half idx = k2*1024 + j*8 + (k&1)*4 + gate
// uint4 element (k2, j): .x=(i,f)@k0 .y=(g,o)@k0 .z=(i,f)@k1 .w=(g,o)@k1
__device__ __half g_W0p[160 * 512];   // layer0: k in [0,32)=Wih0, [32,160)=Whh0
__device__ __half g_W1p[256 * 512];   // layer1: k in [0,128)=Wih1, [128,256)=Whh1
__device__ float  g_B0[512];          // bih0+bhh0, gate-interleaved idx = 4*j+g
__device__ float  g_B1[512];

__global__ void pack_kernel(const float* __restrict__ Wih0, const float* __restrict__ Whh0,
                            const float* __restrict__ bih0, const float* __restrict__ bhh0,
                            const float* __restrict__ Wih1, const float* __restrict__ Whh1,
                            const float* __restrict__ bih1, const float* __restrict__ bhh1)
{
    int idx = blockIdx.x * blockDim.x + threadIdx.x;
    if (idx < 160 * 512) {
        int k2 = idx >> 10, rem = idx & 1023;
        int j = rem >> 3, p = (rem >> 2) & 1, g = rem & 3;
        int k = k2 * 2 + p, row = g * HID + j;
        float w = (k < F_IN) ? Wih0[row * F_IN + k] : Whh0[row * HID + (k - F_IN)];
        g_W0p[idx] = __float2half_rn(w);
    }
    if (idx < 256 * 512) {
        int k2 = idx >> 10, rem = idx & 1023;
        int j = rem >> 3, p = (rem >> 2) & 1, g = rem & 3;
        int k = k2 * 2 + p, row = g * HID + j;
        float w = (k < HID) ? Wih1[row * HID + k] : Whh1[row * HID + (k - HID)];
        g_W1p[idx] = __float2half_rn(w);
    }
    if (idx < 512) {
        int j = idx >> 2, g = idx & 3, row = g * HID + j;
        g_B0[idx] = bih0[row] + bhh0[row];
        g_B1[idx] = bih1[row] + bhh1[row];
    }
}

// ---- packed f32x2 helpers ----
__device__ __forceinline__ void upk2(unsigned long long v, float& lo, float& hi) {
    unsigned int a, b;
    asm("mov.b64 {%0, %1}, %2;" : "=r"(a), "=r"(b) : "l"(v));
    lo = __uint_as_float(a); hi = __uint_as_float(b);
}
__device__ __forceinline__ unsigned long long pkf2(float2 v) {
    unsigned long long r;
    asm("mov.b64 %0, {%1, %2};" : "=l"(r) : "r"(__float_as_uint(v.x)), "r"(__float_as_uint(v.y)));
    return r;
}
__device__ __forceinline__ void fma2(unsigned long long& d, unsigned long long a, unsigned long long b) {
    asm("fma.rn.f32x2 %0, %1, %2, %0;" : "+l"(d) : "l"(a), "l"(b));
}

__device__ __forceinline__ float sigf(float x) {
    return 1.0f / (1.0f + __expf(-x));
}
__device__ __forceinline__ float tanhfast(float x) {
    float cx = fminf(fmaxf(x, -15.f), 15.f);
    float e  = __expf(-2.f * cx);
    return (1.f - e) / (1.f + e);
}

// One uint4 = 2 k-steps of column j's 4 gate weights; acts are (h,h)-duplicated
// float2 so one 16B load per row yields both k's broadcast f32x2 operands.
// accs: [0]=(i,f) rowA, [1]=(g,o) rowA, [2]=(i,f) rowB, [3]=(g,o) rowB
__device__ __forceinline__ void mac2(uint4 wv, const float2* actBase, int strideF2,
                                     int k2, int r0, unsigned long long* accs)
{
    const ulonglong2 avA = *reinterpret_cast<const ulonglong2*>(actBase + (size_t)r0 * strideF2 + 2 * k2);
    const ulonglong2 avB = *reinterpret_cast<const ulonglong2*>(actBase + (size_t)(r0 + 1) * strideF2 + 2 * k2);
    unsigned long long wif0 = pkf2(__half22float2(*reinterpret_cast<const __half2*>(&wv.x)));
    unsigned long long wgo0 = pkf2(__half22float2(*reinterpret_cast<const __half2*>(&wv.y)));
    unsigned long long wif1 = pkf2(__half22float2(*reinterpret_cast<const __half2*>(&wv.z)));
    unsigned long long wgo1 = pkf2(__half22float2(*reinterpret_cast<const __half2*>(&wv.w)));
    fma2(accs[0], wif0, avA.x); fma2(accs[1], wgo0, avA.x);
    fma2(accs[2], wif0, avB.x); fma2(accs[3], wgo0, avB.x);
    fma2(accs[0], wif1, avA.y); fma2(accs[1], wgo1, avA.y);
    fma2(accs[2], wif1, avB.y); fma2(accs[3], wgo1, avB.y);
}

__global__ __launch_bounds__(NTHR, 1)
void lstm_main(const float* __restrict__ x,
               const float* __restrict__ ln_g, const float* __restrict__ ln_b,
               const float* __restrict__ hW1,  const float* __restrict__ hb1,
               const float* __restrict__ hW2,  const float* __restrict__ hb2,
               float* __restrict__ out)
{
    extern __shared__ char dsm[];              // [0,163840)=W0, [163840,204800)=W1[0:20 k2]
    // __align__(16): mac2 does 16-byte vector loads on these; float2 alone only
    // guarantees 8-byte alignment and a misaligned base faults every LDS.128.
    __shared__ __align__(16) float2 a0d[BC][160];  // dup acts: [0:32) x_t, [32:160) h0
    __shared__ __align__(16) float2 a1d[BC][256];  // dup acts: [0:128) h0_new, [128:256) h1
    __shared__ float red[BC][64];
    __shared__ float mv[BC][2];

    const int tid = threadIdx.x;
    const int j   = tid & 127;                 // hidden column
    const int rh  = tid >> 7;                  // row-half: rows 2rh, 2rh+1
    const int r0  = 2 * rh;
    const int bid = blockIdx.x;

    // ---- one-time: stage weights into smem ----
    {
        const uint4* s0 = reinterpret_cast<const uint4*>(g_W0p);
        uint4* d0 = reinterpret_cast<uint4*>(dsm);
        for (int i = tid; i < 80 * 128; i += NTHR) d0[i] = s0[i];
        const uint4* s1 = reinterpret_cast<const uint4*>(g_W1p);
        uint4* d1 = reinterpret_cast<uint4*>(dsm + 160 * 1024);
        for (int i = tid; i < W1S * 128; i += NTHR) d1[i] = s1[i];
    }
    for (int i = tid; i < BC * 160; i += NTHR) (&a0d[0][0])[i] = make_float2(0.f, 0.f);
    for (int i = tid; i < BC * 256; i += NTHR) (&a1d[0][0])[i] = make_float2(0.f, 0.f);

    const uint4* __restrict__ W0s = reinterpret_cast<const uint4*>(dsm);
    const uint4* __restrict__ W1s = reinterpret_cast<const uint4*>(dsm + 160 * 1024);
    const uint4* __restrict__ W1g = reinterpret_cast<const uint4*>(g_W1p);
    const float4 b0v = reinterpret_cast<const float4*>(g_B0)[j];
    const float4 b1v = reinterpret_cast<const float4*>(g_B1)[j];

    float c0[2] = {0.f, 0.f};
    float c1[2] = {0.f, 0.f};

    const float* xbase = x + (size_t)(bid * BC) * T_STEPS * F_IN;
    const int xr = (tid & 127) >> 5, xk = tid & 31;          // tid<128 stages x
    const float* xsrc = xbase + (size_t)xr * T_STEPS * F_IN + xk;

    __syncthreads();   // weights + zeroed state visible

    for (int t = 0; t < T_STEPS; ++t) {
        // stage x_t duplicated (sync A also publishes last step's h1 writes)
        if (tid < 128) {
            float v = xsrc[t * F_IN];
            a0d[xr][xk] = make_float2(v, v);
        }
        __syncthreads();   // A

        // prime the W1 global-stream ring early (weights are static; ~600cyc lead)
        uint4 ring[6];
        #pragma unroll
        for (int q = 0; q < 6; ++q) ring[q] = W1g[(W1S + q) * 128 + j];

        // ---------------- layer 0: full K from smem ----------------
        unsigned long long accs[4] = {0, 0, 0, 0};
        #pragma unroll 4
        for (int k2 = 0; k2 < 80; ++k2) {
            uint4 wv = W0s[k2 * 128 + j];
            mac2(wv, &a0d[0][0], 160, k2, r0, accs);
        }
        __syncthreads();   // B: all a0d reads done before h0 overwrite

        #pragma unroll
        for (int rr = 0; rr < 2; ++rr) {
            float gi, gf, gg, go;
            upk2(accs[2 * rr], gi, gf); upk2(accs[2 * rr + 1], gg, go);
            float ig = sigf(gi + b0v.x), fg = sigf(gf + b0v.y);
            float gv = tanhfast(gg + b0v.z), og = sigf(go + b0v.w);
            c0[rr] = fg * c0[rr] + ig * gv;
            float hh = og * tanhfast(c0[rr]);
            a0d[r0 + rr][32 + j] = make_float2(hh, hh);
            a1d[r0 + rr][j]      = make_float2(hh, hh);
        }
        __syncthreads();   // C: h0_new published

        // ---------------- layer 1: smem slice + streamed remainder ----------------
        accs[0] = accs[1] = accs[2] = accs[3] = 0;
        #pragma unroll 4
        for (int k2 = 0; k2 < W1S; ++k2) {
            uint4 wv = W1s[k2 * 128 + j];
            mac2(wv, &a1d[0][0], 256, k2, r0, accs);
        }
        #pragma unroll 1
        for (int ii = 0; ii < 18; ++ii) {          // 18*6 = 108 = 128-W1S
            int base = W1S + ii * 6;
            #pragma unroll
            for (int q = 0; q < 6; ++q) {
                uint4 wv = ring[q];
                int nk = base + q + 6;
                if (nk < 128) ring[q] = W1g[nk * 128 + j];
                mac2(wv, &a1d[0][0], 256, base + q, r0, accs);
            }
        }
        __syncthreads();   // D: all a1d reads done before h1 overwrite

        #pragma unroll
        for (int rr = 0; rr < 2; ++rr) {
            float gi, gf, gg, go;
            upk2(accs[2 * rr], gi, gf); upk2(accs[2 * rr + 1], gg, go);
            float ig = sigf(gi + b1v.x), fg = sigf(gf + b1v.y);
            float gv = tanhfast(gg + b1v.z), og = sigf(go + b1v.w);
            c1[rr] = fg * c1[rr] + ig * gv;
            float hh = og * tanhfast(c1[rr]);
            a1d[r0 + rr][128 + j] = make_float2(hh, hh);
        }
        // next iteration's sync A publishes h1
    }
    __syncthreads();

    // ---------------- head: LayerNorm -> Linear(64) -> ReLU -> Linear(1) -> sigmoid ----
    if (tid < BC) {
        int r = tid;
        float s = 0.f;
        for (int k = 0; k < HID; ++k) s += a1d[r][128 + k].x;
        float mu = s * (1.f / HID);
        float v = 0.f;
        for (int k = 0; k < HID; ++k) { float d = a1d[r][128 + k].x - mu; v += d * d; }
        v *= (1.f / HID);
        mv[r][0] = mu;
        mv[r][1] = rsqrtf(v + 1e-5f);
    }
    __syncthreads();
    {
        int r = tid >> 6, u = tid & 63;        // 256 threads = 4 rows x 64 units
        float mu = mv[r][0], rs = mv[r][1];
        float acc = hb1[u];
        for (int k = 0; k < HID; ++k) {
            float lnv = (a1d[r][128 + k].x - mu) * rs * ln_g[k] + ln_b[k];
            acc += lnv * hW1[u * HID + k];
        }
        red[r][u] = fmaxf(acc, 0.f);
    }
    __syncthreads();
    if (tid < BC) {
        int r = tid;
        float y = hb2[0];
        for (int u = 0; u < 64; ++u) y += red[r][u] * hW2[u];
        out[bid * BC + r] = sigf(y);
    }
}

extern "C" void kernel_launch(void* const* d_in, const int* in_sizes, int n_in,
                              void* d_out, int out_size)
{
    const float* x    = (const float*)d_in[0];
    const float* Wih0 = (const float*)d_in[1];
    const float* Whh0 = (const float*)d_in[2];
    const float* bih0 = (const float*)d_in[3];
    const float* bhh0 = (const float*)d_in[4];
    const float* Wih1 = (const float*)d_in[5];
    const float* Whh1 = (const float*)d_in[6];
    const float* bih1 = (const float*)d_in[7];
    const float* bhh1 = (const float*)d_in[8];
    const float* ln_g = (const float*)d_in[9];
    const float* ln_b = (const float*)d_in[10];
    const float* W1   = (const float*)d_in[11];
    const float* b1   = (const float*)d_in[12];
    const float* W2   = (const float*)d_in[13];
    const float* b2   = (const float*)d_in[14];
    float* out = (float*)d_out;

    const int dyn_smem = 160 * 1024 + W1S * 2048;   // 163840 + 40960 = 204800
    cudaFuncSetAttribute(lstm_main, cudaFuncAttributeMaxDynamicSharedMemorySize, dyn_smem);

    pack_kernel<<<512, 256>>>(Wih0, Whh0, bih0, bhh0, Wih1, Whh1, bih1, bhh1);
    lstm_main<<<NBLK, NTHR, dyn_smem>>>(x, ln_g, ln_b, W1, b1, W2, b2, out);
}

// round 10
// speedup vs baseline: 1.8635x; 1.1523x over previous
#include <cuda_runtime.h>
#include <cuda_fp16.h>
#include <math.h>

// Problem constants
#define B_TOTAL 512
#define T_STEPS 1024
#define F_IN    32
#define HID     128
#define BC      16                 // batch rows per block = full m16 MMA tile
#define NBLK    (B_TOTAL / BC)     // 32 blocks
#define NTHR    256                // 8 warps; warp w owns gate cols [w*64, w*64+64)
#define ASTR    264                // act row stride in halves (264*2B=528B -> bank period 4)

// ---------------- packed weights (B fragments) ----------------
// mma.sync.m16n8k16.row.col B fragment (k16 x n8, col-major), per lane 2 regs:
//   b0 halves: (k = (lane%4)*2 + {0,1},     n = lane/4)
//   b1 halves: (k = (lane%4)*2 + 8 + {0,1}, n = lane/4)
// We pack per (ktpair p, ntile nt, lane) one uint4 = 8 halves:
//   halves 0..3 = {b0lo,b0hi,b1lo,b1hi} of kt=2p ; halves 4..7 = same of kt=2p+1
// Array index (uint4 units): (p*64 + nt)*32 + lane.
// Gate columns are interleaved: col n = 4*j + g  <->  original W row = g*128 + j.
__device__ __align__(16) __half g_BF0[5 * 64 * 32 * 8];   // L0: K=160 -> 5 ktpairs
__device__ __align__(16) __half g_BF1[8 * 64 * 32 * 8];   // L1: K=256 -> 8 ktpairs
__device__ float g_B0[512];    // bih0+bhh0, gate-interleaved idx = 4*j + g
__device__ float g_B1[512];

__global__ void pack_kernel(const float* __restrict__ Wih0, const float* __restrict__ Whh0,
                            const float* __restrict__ bih0, const float* __restrict__ bhh0,
                            const float* __restrict__ Wih1, const float* __restrict__ Whh1,
                            const float* __restrict__ bih1, const float* __restrict__ bhh1)
{
    int idx = blockIdx.x * blockDim.x + threadIdx.x;   // one thread per packed half
    // L0 fragments: 5*64*32*8 = 81920 halves
    if (idx < 81920) {
        int h8 = idx & 7, o4 = idx >> 3;
        int lane = o4 & 31, ntp = o4 >> 5;
        int nt = ntp & 63, p = ntp >> 6;
        int kt = 2 * p + (h8 >> 2);
        int k  = kt * 16 + (lane & 3) * 2 + ((h8 >> 1) & 1) * 8 + (h8 & 1);
        int n  = nt * 8 + (lane >> 2);
        int row = (n & 3) * HID + (n >> 2);
        float w = (k < F_IN) ? Wih0[row * F_IN + k] : Whh0[row * HID + (k - F_IN)];
        g_BF0[idx] = __float2half_rn(w);
    }
    // L1 fragments: 8*64*32*8 = 131072 halves
    if (idx < 131072) {
        int h8 = idx & 7, o4 = idx >> 3;
        int lane = o4 & 31, ntp = o4 >> 5;
        int nt = ntp & 63, p = ntp >> 6;
        int kt = 2 * p + (h8 >> 2);
        int k  = kt * 16 + (lane & 3) * 2 + ((h8 >> 1) & 1) * 8 + (h8 & 1);
        int n  = nt * 8 + (lane >> 2);
        int row = (n & 3) * HID + (n >> 2);
        float w = (k < HID) ? Wih1[row * HID + k] : Whh1[row * HID + (k - HID)];
        g_BF1[idx] = __float2half_rn(w);
    }
    if (idx < 512) {
        int j = idx >> 2, g = idx & 3, row = g * HID + j;
        g_B0[idx] = bih0[row] + bhh0[row];
        g_B1[idx] = bih1[row] + bhh1[row];
    }
}

// ---------------- PTX helpers ----------------
__device__ __forceinline__ unsigned smem_u32(const void* p) {
    return (unsigned)__cvta_generic_to_shared(p);
}
__device__ __forceinline__ void ldmA(unsigned addr, unsigned& a0, unsigned& a1,
                                     unsigned& a2, unsigned& a3) {
    asm volatile("ldmatrix.sync.aligned.m8n8.x4.shared.b16 {%0,%1,%2,%3}, [%4];"
                 : "=r"(a0), "=r"(a1), "=r"(a2), "=r"(a3) : "r"(addr));
}
__device__ __forceinline__ void mma16816(float& c0, float& c1, float& c2, float& c3,
                                         unsigned a0, unsigned a1, unsigned a2, unsigned a3,
                                         unsigned b0, unsigned b1) {
    asm volatile("mma.sync.aligned.m16n8k16.row.col.f32.f16.f16.f32 "
                 "{%0,%1,%2,%3}, {%4,%5,%6,%7}, {%8,%9}, {%0,%1,%2,%3};"
                 : "+f"(c0), "+f"(c1), "+f"(c2), "+f"(c3)
                 : "r"(a0), "r"(a1), "r"(a2), "r"(a3), "r"(b0), "r"(b1));
}

__device__ __forceinline__ float sigf(float x) {
    return 1.0f / (1.0f + __expf(-x));
}
__device__ __forceinline__ float tanhfast(float x) {
    float cx = fminf(fmaxf(x, -15.f), 15.f);
    float e  = __expf(-2.f * cx);
    return (1.f - e) / (1.f + e);
}

// One LSTM layer's gate GEMM: acc[q][4] over warp's 8 n-tiles, K = 32*P.
template<int P>
__device__ __forceinline__ void layer_mma(const uint4* __restrict__ Bg, unsigned actbase,
                                          const float* sBias, int wid, int lane,
                                          float acc[8][4])
{
    // init accumulators with biases (c0,c1 = cols (lane%4)*2,+1 ; c2,c3 same cols)
    #pragma unroll
    for (int q = 0; q < 8; ++q) {
        const float2 b2 = *reinterpret_cast<const float2*>(sBias + wid * 64 + q * 8 + (lane & 3) * 2);
        acc[q][0] = b2.x; acc[q][1] = b2.y; acc[q][2] = b2.x; acc[q][3] = b2.y;
    }
    const int ntb = wid * 8;
    uint4 bufA[8], bufB[8];
    #pragma unroll
    for (int q = 0; q < 8; ++q) bufA[q] = Bg[(0 * 64 + ntb + q) * 32 + lane];

    // ldmatrix lane address: lanes 0-7 rows0-7 k0 | 8-15 rows8-15 k0 | 16-23 rows0-7 k+8 | 24-31 rows8-15 k+8
    const int lr = (lane & 7) + ((lane >> 3) & 1) * 8;
    const int lc = ((lane >> 4) & 1) * 8;
    const unsigned abase = actbase + (unsigned)(lr * ASTR + lc) * 2u;

    #pragma unroll
    for (int p = 0; p < P; ++p) {
        uint4* cur = (p & 1) ? bufB : bufA;
        uint4* nxt = (p & 1) ? bufA : bufB;
        if (p + 1 < P) {
            #pragma unroll
            for (int q = 0; q < 8; ++q) nxt[q] = Bg[((p + 1) * 64 + ntb + q) * 32 + lane];
        }
        unsigned a0, a1, a2, a3, e0, e1, e2, e3;
        ldmA(abase + (unsigned)(p * 64),      a0, a1, a2, a3);   // kt=2p   (kt*32 bytes)
        ldmA(abase + (unsigned)(p * 64 + 32), e0, e1, e2, e3);   // kt=2p+1
        #pragma unroll
        for (int q = 0; q < 8; ++q)
            mma16816(acc[q][0], acc[q][1], acc[q][2], acc[q][3], a0, a1, a2, a3, cur[q].x, cur[q].y);
        #pragma unroll
        for (int q = 0; q < 8; ++q)
            mma16816(acc[q][0], acc[q][1], acc[q][2], acc[q][3], e0, e1, e2, e3, cur[q].z, cur[q].w);
    }
}

__global__ __launch_bounds__(NTHR, 1)
void lstm_main(const float* __restrict__ x,
               const float* __restrict__ ln_g, const float* __restrict__ ln_b,
               const float* __restrict__ hW1,  const float* __restrict__ hb1,
               const float* __restrict__ hW2,  const float* __restrict__ hb2,
               float* __restrict__ out)
{
    __shared__ __align__(16) __half A0h[BC * ASTR];   // [0:32) x_t, [32:160) h0
    __shared__ __align__(16) __half A1h[BC * ASTR];   // [0:128) h0_new, [128:256) h1
    __shared__ float sB0[512], sB1[512];
    __shared__ float red[BC][64];
    __shared__ float mv[BC][2];

    const int tid  = threadIdx.x;
    const int wid  = tid >> 5;
    const int lane = tid & 31;
    const int bid  = blockIdx.x;

    for (int i = tid; i < BC * ASTR; i += NTHR) { A0h[i] = __half(0); A1h[i] = __half(0); }
    for (int i = tid; i < 512; i += NTHR) { sB0[i] = g_B0[i]; sB1[i] = g_B1[i]; }

    const uint4* __restrict__ BF0 = reinterpret_cast<const uint4*>(g_BF0);
    const uint4* __restrict__ BF1 = reinterpret_cast<const uint4*>(g_BF1);
    const unsigned a0base = smem_u32(A0h);
    const unsigned a1base = smem_u32(A1h);

    // gate-phase ownership: (row, j) fixed per (lane, q)
    const int odd  = lane & 1;
    const int grow = (lane >> 2) + (odd ? 8 : 0);
    const int jb   = wid * 16 + ((lane >> 1) & 1);

    float cst0[8], cst1[8];
    #pragma unroll
    for (int q = 0; q < 8; ++q) { cst0[q] = 0.f; cst1[q] = 0.f; }

    // x staging map: thread -> (row, 2 features)
    const int xrow = tid >> 4, xk = (tid & 15) * 2;
    const float* xsrc = x + ((size_t)(bid * BC + xrow) * T_STEPS) * F_IN + xk;

    __syncthreads();

    for (int t = 0; t < T_STEPS; ++t) {
        // stage x_t as fp16 (sync A also publishes last step's h1 writes)
        {
            const float2 xv = *reinterpret_cast<const float2*>(xsrc + (size_t)t * F_IN);
            *reinterpret_cast<__half2*>(&A0h[xrow * ASTR + xk]) = __floats2half2_rn(xv.x, xv.y);
        }
        __syncthreads();   // A

        // ---------------- layer 0: gates = [x_t, h0] @ W0 ----------------
        float acc[8][4];
        layer_mma<5>(BF0, a0base, sB0, wid, lane, acc);
        __syncthreads();   // B: all A0 reads done before h0 overwrite

        #pragma unroll
        for (int q = 0; q < 8; ++q) {
            float ex0 = __shfl_xor_sync(0xffffffffu, acc[q][0], 1);
            float ex1 = __shfl_xor_sync(0xffffffffu, acc[q][1], 1);
            float ex2 = __shfl_xor_sync(0xffffffffu, acc[q][2], 1);
            float ex3 = __shfl_xor_sync(0xffffffffu, acc[q][3], 1);
            float gi = odd ? ex2 : acc[q][0];
            float gf = odd ? ex3 : acc[q][1];
            float gg = odd ? acc[q][2] : ex0;
            float go = odd ? acc[q][3] : ex1;
            float cn = sigf(gf) * cst0[q] + sigf(gi) * tanhfast(gg);
            cst0[q] = cn;
            __half hh = __float2half_rn(sigf(go) * tanhfast(cn));
            int j = jb + q * 2;
            A0h[grow * ASTR + 32 + j] = hh;
            A1h[grow * ASTR + j]      = hh;
        }
        __syncthreads();   // C: h0_new published

        // ---------------- layer 1: gates = [h0_new, h1] @ W1 ----------------
        layer_mma<8>(BF1, a1base, sB1, wid, lane, acc);
        __syncthreads();   // D: all A1 reads done before h1 overwrite

        #pragma unroll
        for (int q = 0; q < 8; ++q) {
            float ex0 = __shfl_xor_sync(0xffffffffu, acc[q][0], 1);
            float ex1 = __shfl_xor_sync(0xffffffffu, acc[q][1], 1);
            float ex2 = __shfl_xor_sync(0xffffffffu, acc[q][2], 1);
            float ex3 = __shfl_xor_sync(0xffffffffu, acc[q][3], 1);
            float gi = odd ? ex2 : acc[q][0];
            float gf = odd ? ex3 : acc[q][1];
            float gg = odd ? acc[q][2] : ex0;
            float go = odd ? acc[q][3] : ex1;
            float cn = sigf(gf) * cst1[q] + sigf(gi) * tanhfast(gg);
            cst1[q] = cn;
            __half hh = __float2half_rn(sigf(go) * tanhfast(cn));
            int j = jb + q * 2;
            A1h[grow * ASTR + 128 + j] = hh;
        }
        // next iteration's sync A publishes h1
    }
    __syncthreads();

    // ---------------- head: LayerNorm -> Linear(64) -> ReLU -> Linear(1) -> sigmoid ----
    if (tid < BC) {
        int r = tid;
        float s = 0.f;
        for (int k = 0; k < HID; ++k) s += __half2float(A1h[r * ASTR + 128 + k]);
        float mu = s * (1.f / HID);
        float v = 0.f;
        for (int k = 0; k < HID; ++k) {
            float d = __half2float(A1h[r * ASTR + 128 + k]) - mu; v += d * d;
        }
        v *= (1.f / HID);
        mv[r][0] = mu;
        mv[r][1] = rsqrtf(v + 1e-5f);
    }
    __syncthreads();
    #pragma unroll
    for (int it = 0; it < 4; ++it) {
        int idx = tid + it * NTHR;            // 0..1023 = 16 rows x 64 units
        int r = idx >> 6, u = idx & 63;
        float mu = mv[r][0], rs = mv[r][1];
        float acc = hb1[u];
        for (int k = 0; k < HID; ++k) {
            float hv  = __half2float(A1h[r * ASTR + 128 + k]);
            float lnv = (hv - mu) * rs * ln_g[k] + ln_b[k];
            acc += lnv * hW1[u * HID + k];
        }
        red[r][u] = fmaxf(acc, 0.f);
    }
    __syncthreads();
    if (tid < BC) {
        int r = tid;
        float y = hb2[0];
        for (int u = 0; u < 64; ++u) y += red[r][u] * hW2[u];
        out[bid * BC + r] = sigf(y);
    }
}

extern "C" void kernel_launch(void* const* d_in, const int* in_sizes, int n_in,
                              void* d_out, int out_size)
{
    const float* x    = (const float*)d_in[0];
    const float* Wih0 = (const float*)d_in[1];
    const float* Whh0 = (const float*)d_in[2];
    const float* bih0 = (const float*)d_in[3];
    const float* bhh0 = (const float*)d_in[4];
    const float* Wih1 = (const float*)d_in[5];
    const float* Whh1 = (const float*)d_in[6];
    const float* bih1 = (const float*)d_in[7];
    const float* bhh1 = (const float*)d_in[8];
    const float* ln_g = (const float*)d_in[9];
    const float* ln_b = (const float*)d_in[10];
    const float* W1   = (const float*)d_in[11];
    const float* b1   = (const float*)d_in[12];
    const float* W2   = (const float*)d_in[13];
    const float* b2   = (const float*)d_in[14];
    float* out = (float*)d_out;

    pack_kernel<<<512, 256>>>(Wih0, Whh0, bih0, bhh0, Wih1, Whh1, bih1, bhh1);
    lstm_main<<<NBLK, NTHR>>>(x, ln_g, ln_b, W1, b1, W2, b2, out);
}

// round 12
// speedup vs baseline: 3.8085x; 2.0437x over previous
#include <cuda_runtime.h>
#include <cuda_fp16.h>
#include <math.h>

// Problem constants
#define B_TOTAL 512
#define T_STEPS 1024
#define F_IN    32
#define HID     128
#define BC      16                 // batch rows per block = full m16 MMA tile
#define NBLK    (B_TOTAL / BC)     // 32 blocks
#define NTHR    256                // 8 warps; warp w owns gate cols [w*64, w*64+64)
#define ASTR    264                // act row stride in halves

// Dynamic smem layout (bytes)
#define OFF_W0  0                  // W0 fragments: 10240 uint4 = 163840
#define OFF_W1S 163840             // W1 p=0 fragments: 2048 uint4 = 32768
#define OFF_A0  196608             // A0 acts: 16*264*2 = 8448
#define OFF_A1  205056             // A1 acts: 8448  -> total 213504
#define DYN_SMEM 213504

// ---------------- packed weights (B fragments) ----------------
// mma.sync.m16n8k16.row.col B fragment (k16 x n8, col-major), per lane 2 regs:
//   b0 halves: (k = (lane%4)*2 + {0,1},     n = lane/4)
//   b1 halves: (k = (lane%4)*2 + 8 + {0,1}, n = lane/4)
// Packed per (ktpair p, ntile nt, lane) one uint4 = 8 halves:
//   halves 0..3 = {b0lo,b0hi,b1lo,b1hi} of kt=2p ; halves 4..7 = same of kt=2p+1
// Index (uint4 units): (p*64 + nt)*32 + lane. Gate cols interleaved: n = 4*j+g.
__device__ __align__(16) __half g_BF0[5 * 64 * 32 * 8];   // L0: K=160 -> 5 ktpairs
__device__ __align__(16) __half g_BF1[8 * 64 * 32 * 8];   // L1: K=256 -> 8 ktpairs
__device__ float g_B0[512];    // bih0+bhh0, gate-interleaved idx = 4*j + g
__device__ float g_B1[512];

__global__ void pack_kernel(const float* __restrict__ Wih0, const float* __restrict__ Whh0,
                            const float* __restrict__ bih0, const float* __restrict__ bhh0,
                            const float* __restrict__ Wih1, const float* __restrict__ Whh1,
                            const float* __restrict__ bih1, const float* __restrict__ bhh1)
{
    int idx = blockIdx.x * blockDim.x + threadIdx.x;
    if (idx < 81920) {
        int h8 = idx & 7, o4 = idx >> 3;
        int lane = o4 & 31, ntp = o4 >> 5;
        int nt = ntp & 63, p = ntp >> 6;
        int kt = 2 * p + (h8 >> 2);
        int k  = kt * 16 + (lane & 3) * 2 + ((h8 >> 1) & 1) * 8 + (h8 & 1);
        int n  = nt * 8 + (lane >> 2);
        int row = (n & 3) * HID + (n >> 2);
        float w = (k < F_IN) ? Wih0[row * F_IN + k] : Whh0[row * HID + (k - F_IN)];
        g_BF0[idx] = __float2half_rn(w);
    }
    if (idx < 131072) {
        int h8 = idx & 7, o4 = idx >> 3;
        int lane = o4 & 31, ntp = o4 >> 5;
        int nt = ntp & 63, p = ntp >> 6;
        int kt = 2 * p + (h8 >> 2);
        int k  = kt * 16 + (lane & 3) * 2 + ((h8 >> 1) & 1) * 8 + (h8 & 1);
        int n  = nt * 8 + (lane >> 2);
        int row = (n & 3) * HID + (n >> 2);
        float w = (k < HID) ? Wih1[row * HID + k] : Whh1[row * HID + (k - HID)];
        g_BF1[idx] = __float2half_rn(w);
    }
    if (idx < 512) {
        int j = idx >> 2, g = idx & 3, row = g * HID + j;
        g_B0[idx] = bih0[row] + bhh0[row];
        g_B1[idx] = bih1[row] + bhh1[row];
    }
}

// ---------------- PTX helpers ----------------
__device__ __forceinline__ unsigned smem_u32(const void* p) {
    return (unsigned)__cvta_generic_to_shared(p);
}
__device__ __forceinline__ void ldmA(unsigned addr, unsigned& a0, unsigned& a1,
                                     unsigned& a2, unsigned& a3) {
    asm volatile("ldmatrix.sync.aligned.m8n8.x4.shared.b16 {%0,%1,%2,%3}, [%4];"
                 : "=r"(a0), "=r"(a1), "=r"(a2), "=r"(a3) : "r"(addr));
}
__device__ __forceinline__ void mma16816(float& c0, float& c1, float& c2, float& c3,
                                         unsigned a0, unsigned a1, unsigned a2, unsigned a3,
                                         unsigned b0, unsigned b1) {
    asm volatile("mma.sync.aligned.m16n8k16.row.col.f32.f16.f16.f32 "
                 "{%0,%1,%2,%3}, {%4,%5,%6,%7}, {%8,%9}, {%0,%1,%2,%3};"
                 : "+f"(c0), "+f"(c1), "+f"(c2), "+f"(c3)
                 : "r"(a0), "r"(a1), "r"(a2), "r"(a3), "r"(b0), "r"(b1));
}
__device__ __forceinline__ float tanha(float x) {
    float r;
    asm("tanh.approx.f32 %0, %1;" : "=f"(r) : "f"(x));
    return r;
}
__device__ __forceinline__ float sigt(float x) {        // sigmoid via tanh
    return fmaf(0.5f, tanha(0.5f * x), 0.5f);
}

__global__ __launch_bounds__(NTHR, 1)
void lstm_main(const float* __restrict__ x,
               const float* __restrict__ ln_g, const float* __restrict__ ln_b,
               const float* __restrict__ hW1,  const float* __restrict__ hb1,
               const float* __restrict__ hW2,  const float* __restrict__ hb2,
               float* __restrict__ out)
{
    extern __shared__ __align__(16) char dsm[];
    uint4*  W0s = reinterpret_cast<uint4*>(dsm + OFF_W0);
    uint4*  W1s = reinterpret_cast<uint4*>(dsm + OFF_W1S);
    __half* A0h = reinterpret_cast<__half*>(dsm + OFF_A0);   // [0:32) x_t, [32:160) h0
    __half* A1h = reinterpret_cast<__half*>(dsm + OFF_A1);   // [0:128) h0_new, [128:256) h1
    __shared__ float red[BC][64];
    __shared__ float mv[BC][2];

    const int tid  = threadIdx.x;
    const int wid  = tid >> 5;
    const int lane = tid & 31;
    const int bid  = blockIdx.x;
    const int ntb  = wid * 8;

    // ---- one-time: stage W0 (all) + W1 p=0 into smem; zero acts ----
    {
        const uint4* s0 = reinterpret_cast<const uint4*>(g_BF0);
        for (int i = tid; i < 10240; i += NTHR) W0s[i] = s0[i];
        const uint4* s1 = reinterpret_cast<const uint4*>(g_BF1);
        for (int i = tid; i < 2048; i += NTHR) W1s[i] = s1[i];
    }
    for (int i = tid; i < BC * ASTR; i += NTHR) { A0h[i] = __half(0); A1h[i] = __half(0); }

    const uint4* __restrict__ BF1 = reinterpret_cast<const uint4*>(g_BF1);
    const unsigned a0base = smem_u32(A0h);
    const unsigned a1base = smem_u32(A1h);

    // biases in registers (acc init)
    float2 bias0[8], bias1[8];
    #pragma unroll
    for (int q = 0; q < 8; ++q) {
        bias0[q] = *reinterpret_cast<const float2*>(g_B0 + wid * 64 + q * 8 + (lane & 3) * 2);
        bias1[q] = *reinterpret_cast<const float2*>(g_B1 + wid * 64 + q * 8 + (lane & 3) * 2);
    }

    // gate-phase ownership for elementwise: (row, j) fixed per (lane, q)
    const int odd  = lane & 1;
    const int grow = (lane >> 2) + (odd ? 8 : 0);
    const int jb   = wid * 16 + ((lane >> 1) & 1);

    float cst0[8], cst1[8];
    #pragma unroll
    for (int q = 0; q < 8; ++q) { cst0[q] = 0.f; cst1[q] = 0.f; }

    // x staging: thread -> (row, 2 features); prefetch one step ahead
    const int xrow = tid >> 4, xk = (tid & 15) * 2;
    const float* xsrc = x + ((size_t)(bid * BC + xrow) * T_STEPS) * F_IN + xk;
    float2 xn = *reinterpret_cast<const float2*>(xsrc);      // t = 0

    // ldmatrix lane address bases
    const int lr = (lane & 7) + ((lane >> 3) & 1) * 8;
    const int lc = ((lane >> 4) & 1) * 8;
    const unsigned ab0 = a0base + (unsigned)(lr * ASTR + lc) * 2u;
    const unsigned ab1 = a1base + (unsigned)(lr * ASTR + lc) * 2u;

    __syncthreads();

    for (int t = 0; t < T_STEPS; ++t) {
        // publish x_t (prefetched last iter); sync A also publishes h1 writes
        *reinterpret_cast<__half2*>(&A0h[xrow * ASTR + xk]) = __floats2half2_rn(xn.x, xn.y);
        __syncthreads();   // A

        // prefetch x for t+1 (independent, long cover)
        if (t + 1 < T_STEPS)
            xn = *reinterpret_cast<const float2*>(xsrc + (size_t)(t + 1) * F_IN);

        // ---------------- layer 0: gates = [x_t, h0] @ W0 (smem weights) ----------------
        float acc[8][4];
        #pragma unroll
        for (int q = 0; q < 8; ++q) {
            acc[q][0] = bias0[q].x; acc[q][1] = bias0[q].y;
            acc[q][2] = bias0[q].x; acc[q][3] = bias0[q].y;
        }
        #pragma unroll
        for (int p = 0; p < 5; ++p) {
            unsigned a0, a1, a2, a3, e0, e1, e2, e3;
            ldmA(ab0 + (unsigned)(p * 64),      a0, a1, a2, a3);
            ldmA(ab0 + (unsigned)(p * 64 + 32), e0, e1, e2, e3);
            #pragma unroll
            for (int q = 0; q < 8; ++q) {
                uint4 wv = W0s[(p * 64 + ntb + q) * 32 + lane];
                mma16816(acc[q][0], acc[q][1], acc[q][2], acc[q][3], a0, a1, a2, a3, wv.x, wv.y);
                mma16816(acc[q][0], acc[q][1], acc[q][2], acc[q][3], e0, e1, e2, e3, wv.z, wv.w);
            }
        }

        // prime W1 stream ring: p = 1,2 (consumed after elementwise + 2 barriers)
        uint4 ring[2][8];
        #pragma unroll
        for (int s = 0; s < 2; ++s)
            #pragma unroll
            for (int q = 0; q < 8; ++q)
                ring[s][q] = BF1[((s + 1) * 64 + ntb + q) * 32 + lane];

        __syncthreads();   // B: all A0 reads done before h0 overwrite

        #pragma unroll
        for (int q = 0; q < 8; ++q) {
            float ex0 = __shfl_xor_sync(0xffffffffu, acc[q][0], 1);
            float ex1 = __shfl_xor_sync(0xffffffffu, acc[q][1], 1);
            float ex2 = __shfl_xor_sync(0xffffffffu, acc[q][2], 1);
            float ex3 = __shfl_xor_sync(0xffffffffu, acc[q][3], 1);
            float gi = odd ? ex2 : acc[q][0];
            float gf = odd ? ex3 : acc[q][1];
            float gg = odd ? acc[q][2] : ex0;
            float go = odd ? acc[q][3] : ex1;
            float cn = sigt(gf) * cst0[q] + sigt(gi) * tanha(gg);
            cst0[q] = cn;
            __half hh = __float2half_rn(sigt(go) * tanha(cn));
            int j = jb + q * 2;
            A0h[grow * ASTR + 32 + j] = hh;
            A1h[grow * ASTR + j]      = hh;
        }
        __syncthreads();   // C: h0_new published

        // ---------------- layer 1: gates = [h0_new, h1] @ W1 ----------------
        #pragma unroll
        for (int q = 0; q < 8; ++q) {
            acc[q][0] = bias1[q].x; acc[q][1] = bias1[q].y;
            acc[q][2] = bias1[q].x; acc[q][3] = bias1[q].y;
        }
        // p = 0 from smem
        {
            unsigned a0, a1, a2, a3, e0, e1, e2, e3;
            ldmA(ab1,      a0, a1, a2, a3);
            ldmA(ab1 + 32, e0, e1, e2, e3);
            #pragma unroll
            for (int q = 0; q < 8; ++q) {
                uint4 wv = W1s[(ntb + q) * 32 + lane];
                mma16816(acc[q][0], acc[q][1], acc[q][2], acc[q][3], a0, a1, a2, a3, wv.x, wv.y);
                mma16816(acc[q][0], acc[q][1], acc[q][2], acc[q][3], e0, e1, e2, e3, wv.z, wv.w);
            }
        }
        // p = 1..7 streamed through the 2-slot ring (reload p+2, ~1 full p of cover)
        #pragma unroll
        for (int p = 1; p < 8; ++p) {
            const int s = (p - 1) & 1;
            unsigned a0, a1, a2, a3, e0, e1, e2, e3;
            ldmA(ab1 + (unsigned)(p * 64),      a0, a1, a2, a3);
            ldmA(ab1 + (unsigned)(p * 64 + 32), e0, e1, e2, e3);
            uint4 wv0 = ring[s][0];
            if (p + 2 < 8) {
                #pragma unroll
                for (int q = 0; q < 8; ++q) {
                    uint4 wv = ring[s][q];
                    ring[s][q] = BF1[((p + 2) * 64 + ntb + q) * 32 + lane];
                    mma16816(acc[q][0], acc[q][1], acc[q][2], acc[q][3], a0, a1, a2, a3, wv.x, wv.y);
                    mma16816(acc[q][0], acc[q][1], acc[q][2], acc[q][3], e0, e1, e2, e3, wv.z, wv.w);
                }
            } else {
                #pragma unroll
                for (int q = 0; q < 8; ++q) {
                    uint4 wv = ring[s][q];
                    mma16816(acc[q][0], acc[q][1], acc[q][2], acc[q][3], a0, a1, a2, a3, wv.x, wv.y);
                    mma16816(acc[q][0], acc[q][1], acc[q][2], acc[q][3], e0, e1, e2, e3, wv.z, wv.w);
                }
            }
            (void)wv0;
        }
        __syncthreads();   // D: all A1 reads done before h1 overwrite

        #pragma unroll
        for (int q = 0; q < 8; ++q) {
            float ex0 = __shfl_xor_sync(0xffffffffu, acc[q][0], 1);
            float ex1 = __shfl_xor_sync(0xffffffffu, acc[q][1], 1);
            float ex2 = __shfl_xor_sync(0xffffffffu, acc[q][2], 1);
            float ex3 = __shfl_xor_sync(0xffffffffu, acc[q][3], 1);
            float gi = odd ? ex2 : acc[q][0];
            float gf = odd ? ex3 : acc[q][1];
            float gg = odd ? acc[q][2] : ex0;
            float go = odd ? acc[q][3] : ex1;
            float cn = sigt(gf) * cst1[q] + sigt(gi) * tanha(gg);
            cst1[q] = cn;
            __half hh = __float2half_rn(sigt(go) * tanha(cn));
            int j = jb + q * 2;
            A1h[grow * ASTR + 128 + j] = hh;
        }
        // next iteration's sync A publishes h1
    }
    __syncthreads();

    // ---------------- head: LayerNorm -> Linear(64) -> ReLU -> Linear(1) -> sigmoid ----
    if (tid < BC) {
        int r = tid;
        float s = 0.f;
        for (int k = 0; k < HID; ++k) s += __half2float(A1h[r * ASTR + 128 + k]);
        float mu = s * (1.f / HID);
        float v = 0.f;
        for (int k = 0; k < HID; ++k) {
            float d = __half2float(A1h[r * ASTR + 128 + k]) - mu; v += d * d;
        }
        v *= (1.f / HID);
        mv[r][0] = mu;
        mv[r][1] = rsqrtf(v + 1e-5f);
    }
    __syncthreads();
    #pragma unroll
    for (int it = 0; it < 4; ++it) {
        int idx = tid + it * NTHR;            // 0..1023 = 16 rows x 64 units
        int r = idx >> 6, u = idx & 63;
        float mu = mv[r][0], rs = mv[r][1];
        float acc = hb1[u];
        for (int k = 0; k < HID; ++k) {
            float hv  = __half2float(A1h[r * ASTR + 128 + k]);
            float lnv = (hv - mu) * rs * ln_g[k] + ln_b[k];
            acc += lnv * hW1[u * HID + k];
        }
        red[r][u] = fmaxf(acc, 0.f);
    }
    __syncthreads();
    if (tid < BC) {
        int r = tid;
        float y = hb2[0];
        for (int u = 0; u < 64; ++u) y += red[r][u] * hW2[u];
        out[bid * BC + r] = 1.0f / (1.0f + __expf(-y));
    }
}

extern "C" void kernel_launch(void* const* d_in, const int* in_sizes, int n_in,
                              void* d_out, int out_size)
{
    const float* x    = (const float*)d_in[0];
    const float* Wih0 = (const float*)d_in[1];
    const float* Whh0 = (const float*)d_in[2];
    const float* bih0 = (const float*)d_in[3];
    const float* bhh0 = (const float*)d_in[4];
    const float* Wih1 = (const float*)d_in[5];
    const float* Whh1 = (const float*)d_in[6];
    const float* bih1 = (const float*)d_in[7];
    const float* bhh1 = (const float*)d_in[8];
    const float* ln_g = (const float*)d_in[9];
    const float* ln_b = (const float*)d_in[10];
    const float* W1   = (const float*)d_in[11];
    const float* b1   = (const float*)d_in[12];
    const float* W2   = (const float*)d_in[13];
    const float* b2   = (const float*)d_in[14];
    float* out = (float*)d_out;

    cudaFuncSetAttribute(lstm_main, cudaFuncAttributeMaxDynamicSharedMemorySize, DYN_SMEM);

    pack_kernel<<<512, 256>>>(Wih0, Whh0, bih0, bhh0, Wih1, Whh1, bih1, bhh1);
    lstm_main<<<NBLK, NTHR, DYN_SMEM>>>(x, ln_g, ln_b, W1, b1, W2, b2, out);
}